// round 14
// baseline (speedup 1.0000x reference)
#include <cuda_runtime.h>
#include <cuda_fp16.h>
#include <math.h>
#include <stdint.h>

#define B_  8
#define N_  4096
#define C_  1024
#define H_  16
#define HF_ 2048
#define M_  (B_*N_)   // 32768
#define QS_ 3072      // fused qkv row stride

// ---------------- scratch (device globals) ----------------
__device__ __half g_h  [(size_t)M_*C_];                       // ln1 out (fp16)
__device__ float  g_qkv[(size_t)M_*QS_];                      // q|k|v fused (fp32)
__device__ __half g_o  [(size_t)M_*C_];                       // scrambled attn out (fp16)
__device__ float  g_x1 [(size_t)M_*C_];
__device__ __half g_h2 [(size_t)M_*C_];
__device__ __half g_ff [(size_t)M_*HF_];
// transposed fp16 weights, [N,K] row-major (K contiguous)
__device__ __half g_wqkv[(size_t)QS_*C_];   // [3072, 1024] rows: q then k then v
__device__ __half g_wp[C_*C_];
__device__ __half g_w1[(size_t)C_*HF_];     // [HF, C]
__device__ __half g_w2[(size_t)C_*HF_];     // [C, HF]

// ---------------- PTX helpers ----------------
#define SWZ(x) ((x) ^ (((x) >> 3) & 0x70))

__device__ __forceinline__ uint32_t s2u(const void* p) {
    uint32_t a;
    asm("{ .reg .u64 t; cvta.to.shared.u64 t, %1; cvt.u32.u64 %0, t; }" : "=r"(a) : "l"(p));
    return a;
}
__device__ __forceinline__ void cpa16(uint32_t d, const void* s) {
    asm volatile("cp.async.cg.shared.global [%0], [%1], 16;" :: "r"(d), "l"(s));
}
__device__ __forceinline__ void cp_commit() { asm volatile("cp.async.commit_group;"); }
__device__ __forceinline__ void cp_wait1()  { asm volatile("cp.async.wait_group 1;"); }
__device__ __forceinline__ void cp_wait0()  { asm volatile("cp.async.wait_group 0;"); }

__device__ __forceinline__ void ldsm_x4(uint32_t* r, uint32_t a) {
    asm volatile("ldmatrix.sync.aligned.m8n8.x4.shared.b16 {%0,%1,%2,%3}, [%4];"
                 : "=r"(r[0]), "=r"(r[1]), "=r"(r[2]), "=r"(r[3]) : "r"(a));
}
__device__ __forceinline__ void mma16816(float* c, const uint32_t* a, const uint32_t* b) {
    asm volatile("mma.sync.aligned.m16n8k16.row.col.f32.f16.f16.f32 "
                 "{%0,%1,%2,%3}, {%4,%5,%6,%7}, {%8,%9}, {%0,%1,%2,%3};"
                 : "+f"(c[0]), "+f"(c[1]), "+f"(c[2]), "+f"(c[3])
                 : "r"(a[0]), "r"(a[1]), "r"(a[2]), "r"(a[3]), "r"(b[0]), "r"(b[1]));
}
// packed f32x2 FMA (sm_103)
__device__ __forceinline__ unsigned long long pack2(float lo, float hi) {
    unsigned long long r;
    asm("mov.b64 %0, {%1, %2};" : "=l"(r) : "f"(lo), "f"(hi));
    return r;
}
__device__ __forceinline__ void fma2(unsigned long long& c, unsigned long long a,
                                     unsigned long long b) {
    asm("fma.rn.f32x2 %0, %1, %2, %0;" : "+l"(c) : "l"(a), "l"(b));
}
__device__ __forceinline__ float2 unpack2(unsigned long long p) {
    float2 r;
    asm("mov.b64 {%0, %1}, %2;" : "=f"(r.x), "=f"(r.y) : "l"(p));
    return r;
}

// ---------------- batched weight transpose (fp32 [K,N] -> fp16 [N,K]) -------------
__device__ __forceinline__ void wtrans_tile(const float* __restrict__ W, int K, int N,
                                            __half* __restrict__ Wt) {
    __shared__ float tile[32][33];
    const int n0 = blockIdx.x * 32, k0 = blockIdx.y * 32;
    const int tx = threadIdx.x, ty = threadIdx.y;
    for (int i = ty; i < 32; i += 8)
        tile[i][tx] = W[(size_t)(k0 + i) * N + n0 + tx];
    __syncthreads();
    for (int i = ty; i < 32; i += 8)
        Wt[(size_t)(n0 + i) * K + k0 + tx] = __float2half_rn(tile[tx][i]);
}
__global__ void wtrans4(const float* __restrict__ wq, const float* __restrict__ wk,
                        const float* __restrict__ wv, const float* __restrict__ wp,
                        __half* __restrict__ wqkv, __half* __restrict__ wpd) {
    const int z = blockIdx.z;
    const float* W = (z == 0) ? wq : (z == 1) ? wk : (z == 2) ? wv : wp;
    __half* dst = (z < 3) ? (wqkv + (size_t)z * C_ * C_) : wpd;
    wtrans_tile(W, C_, C_, dst);
}
__global__ void wtrans2(const float* __restrict__ fc1, const float* __restrict__ fc2,
                        __half* __restrict__ w1, __half* __restrict__ w2) {
    const int z = blockIdx.z;
    if (z == 0) {  // fc1 [C, HF] -> [HF, C]
        if (blockIdx.y >= C_ / 32) return;
        wtrans_tile(fc1, C_, HF_, w1);
    } else {       // fc2 [HF, C] -> [C, HF]
        if (blockIdx.x >= C_ / 32) return;
        wtrans_tile(fc2, HF_, C_, w2);
    }
}

// ---------------- LayerNorm (fp32 in, fp16 out) ----------------
__global__ void __launch_bounds__(256) ln_half(const float* __restrict__ x,
                                               const float* __restrict__ g,
                                               const float* __restrict__ b,
                                               __half* __restrict__ out) {
    const size_t row = blockIdx.x;
    const int t = threadIdx.x;
    float4 v = ((const float4*)(x + row * C_))[t];

    float s  = v.x + v.y + v.z + v.w;
    float sq = v.x * v.x + v.y * v.y + v.z * v.z + v.w * v.w;
    #pragma unroll
    for (int o = 16; o; o >>= 1) {
        s  += __shfl_xor_sync(0xffffffffu, s, o);
        sq += __shfl_xor_sync(0xffffffffu, sq, o);
    }
    __shared__ float ss[8], ssq[8];
    if ((t & 31) == 0) { ss[t >> 5] = s; ssq[t >> 5] = sq; }
    __syncthreads();
    s = 0.f; sq = 0.f;
    #pragma unroll
    for (int i = 0; i < 8; i++) { s += ss[i]; sq += ssq[i]; }

    const float mu  = s * (1.0f / C_);
    const float var = sq * (1.0f / C_) - mu * mu;
    const float rs  = rsqrtf(var + 1e-5f);

    float4 gg = ((const float4*)g)[t];
    float4 bb = ((const float4*)b)[t];
    __half2 h01 = __floats2half2_rn((v.x - mu) * rs * gg.x + bb.x,
                                    (v.y - mu) * rs * gg.y + bb.y);
    __half2 h23 = __floats2half2_rn((v.z - mu) * rs * gg.z + bb.z,
                                    (v.w - mu) * rs * gg.w + bb.w);
    uint2 pk; pk.x = *(uint32_t*)&h01; pk.y = *(uint32_t*)&h23;
    *(uint2*)(out + row * C_ + t * 4) = pk;
}

// ---------------- HMMA GEMM: 128x128 tile, BK=64, 3-stage cp.async ------------------
// Frag double-buffering across ks; fill spread over ks steps; direct-frag epilogue.
// EPI: 0 = fp32 out; 1 = +bias +resid, fp32 out; 2 = +bias, exact GELU, fp16 out.
template <int EPI>
__global__ void __launch_bounds__(256) hgemm(const __half* __restrict__ A,
                                             const __half* __restrict__ Bt,
                                             const float* __restrict__ bias,
                                             const float* __restrict__ resid,
                                             float* __restrict__ outF,
                                             __half* __restrict__ outH,
                                             int K, int N) {
    extern __shared__ char smem[];
    const uint32_t sb = s2u(smem);

    const int t = threadIdx.x;
    const int lane = t & 31, wid = t >> 5;
    const int wm = wid & 1, wn = wid >> 1;     // warp grid 2(m) x 4(n)
    const int bm = blockIdx.y << 7;
    const int bn = blockIdx.x << 7;
    const int NK = K >> 6;

    float acc[4][4][4];
    #pragma unroll
    for (int i = 0; i < 4; i++)
        #pragma unroll
        for (int j = 0; j < 4; j++)
            #pragma unroll
            for (int e = 0; e < 4; e++) acc[i][j][e] = 0.f;

    // per-thread gmem load geometry
    const uint32_t swz0 = SWZ((uint32_t)((t >> 3) * 128 + (t & 7) * 16));
    const __half* gA = A  + (size_t)(bm + (t >> 3)) * K + (t & 7) * 8;
    const __half* gB = Bt + (size_t)(bn + (t >> 3)) * K + (t & 7) * 8;
    const size_t lstride = (size_t)32 * K;

    auto fill_all = [&](int stage, int k0) {
        const uint32_t base = sb + stage * 32768;
        #pragma unroll
        for (int l = 0; l < 4; l++)
            cpa16(base + swz0 + l * 4096, gA + l * lstride + k0);
        #pragma unroll
        for (int l = 0; l < 4; l++)
            cpa16(base + 16384 + swz0 + l * 4096, gB + l * lstride + k0);
        cp_commit();
    };
    // two of the eight loads (pair p in 0..3): A[l=p] and B[l=p]
    auto fill_pair = [&](int stage, int k0, int p) {
        const uint32_t base = sb + stage * 32768;
        cpa16(base + swz0 + p * 4096, gA + p * lstride + k0);
        cpa16(base + 16384 + swz0 + p * 4096, gB + p * lstride + k0);
    };

    fill_all(0, 0);
    fill_all(1, 64);

    // ldsm address precompute
    const uint32_t aRow = (uint32_t)(wm * 64 + (lane & 15));
    const uint32_t aColHalf = (uint32_t)((lane >> 4) * 16);
    const uint32_t bRow = (uint32_t)(wn * 32 + ((lane >> 4) & 1) * 8 + (lane & 7));
    const uint32_t bColHalf = (uint32_t)(((lane >> 3) & 1) * 16);

    uint32_t afr[2][4][4], bfr[2][4][2];

    auto ldfrag = [&](int fb, int ks, uint32_t aB, uint32_t bB) {
        const uint32_t kc = (uint32_t)(ks * 32);
        #pragma unroll
        for (int i = 0; i < 4; i++) {
            uint32_t off = (aRow + i * 16) * 128 + kc + aColHalf;
            ldsm_x4(afr[fb][i], aB + SWZ(off));
        }
        #pragma unroll
        for (int jp = 0; jp < 2; jp++) {
            uint32_t off = (bRow + jp * 16) * 128 + kc + bColHalf;
            uint32_t r[4];
            ldsm_x4(r, bB + SWZ(off));
            bfr[fb][jp * 2][0]     = r[0]; bfr[fb][jp * 2][1]     = r[1];
            bfr[fb][jp * 2 + 1][0] = r[2]; bfr[fb][jp * 2 + 1][1] = r[3];
        }
    };

    for (int ch = 0; ch < NK; ch++) {
        const int buf = ch % 3;
        if (ch == NK - 1) cp_wait0(); else cp_wait1();
        __syncthreads();
        const bool need = (ch + 2 < NK);
        const int fstage = (ch + 2) % 3;
        const int fk0 = (ch + 2) << 6;

        const uint32_t aB = sb + buf * 32768;
        const uint32_t bB = aB + 16384;
        ldfrag(0, 0, aB, bB);
        #pragma unroll
        for (int ks = 0; ks < 4; ks++) {
            const int cur = ks & 1;
            if (ks < 3) ldfrag(cur ^ 1, ks + 1, aB, bB);
            if (need) fill_pair(fstage, fk0, ks);   // spread gmem prefetch
            #pragma unroll
            for (int i = 0; i < 4; i++)
                #pragma unroll
                for (int j = 0; j < 4; j++)
                    mma16816(acc[i][j], afr[cur][i], bfr[cur][j]);
        }
        if (need) cp_commit();
    }

    // -------- epilogue: direct fragment -> gmem (no smem staging) --------
    #pragma unroll
    for (int i = 0; i < 4; i++) {
        const int r0 = bm + wm * 64 + i * 16 + (lane >> 2);
        #pragma unroll
        for (int j = 0; j < 4; j++) {
            const int c0 = bn + wn * 32 + j * 8 + 2 * (lane & 3);
            const size_t go0 = (size_t)r0 * N + c0;
            const size_t go1 = (size_t)(r0 + 8) * N + c0;
            float v0 = acc[i][j][0], v1 = acc[i][j][1];
            float v2 = acc[i][j][2], v3 = acc[i][j][3];
            if (EPI == 0) {
                *(float2*)(outF + go0) = make_float2(v0, v1);
                *(float2*)(outF + go1) = make_float2(v2, v3);
            } else if (EPI == 1) {
                const float2 bb = *(const float2*)(bias + c0);
                const float2 ra = *(const float2*)(resid + go0);
                const float2 rb = *(const float2*)(resid + go1);
                *(float2*)(outF + go0) = make_float2(v0 + bb.x + ra.x, v1 + bb.y + ra.y);
                *(float2*)(outF + go1) = make_float2(v2 + bb.x + rb.x, v3 + bb.y + rb.y);
            } else {
                const float2 bb = *(const float2*)(bias + c0);
                const float ki = 0.70710678118654752f;
                float x0 = v0 + bb.x, x1 = v1 + bb.y, x2 = v2 + bb.x, x3 = v3 + bb.y;
                x0 = 0.5f * x0 * (1.0f + erff(x0 * ki));
                x1 = 0.5f * x1 * (1.0f + erff(x1 * ki));
                x2 = 0.5f * x2 * (1.0f + erff(x2 * ki));
                x3 = 0.5f * x3 * (1.0f + erff(x3 * ki));
                __half2 p0 = __floats2half2_rn(x0, x1);
                __half2 p1 = __floats2half2_rn(x2, x3);
                *(uint32_t*)(outH + go0) = *(uint32_t*)&p0;
                *(uint32_t*)(outH + go1) = *(uint32_t*)&p1;
            }
        }
    }
}

// ---------------- fused attention (fp32 qkv in [M,3072], fp16 scrambled out) --------
// o_merged[b, e*64 + h*4 + (n>>10), n&1023] = o[b,h,e,n]
__global__ void __launch_bounds__(256) attn_kernel(const float* __restrict__ qkv,
                                                   __half* __restrict__ o) {
    extern __shared__ float sm[];
    float* S  = sm;                         // 64*64
    float* b0 = sm + 64 * 64;               // 64*68
    float* b1 = sm + 64 * 64 + 64 * 68;     // 64*68

    const int bh = blockIdx.x;
    const int b = bh >> 4, h = bh & 15;
    const size_t base = (size_t)b * ((size_t)N_ * QS_) + (size_t)h * 64;
    const int t  = threadIdx.x;
    const int tx = t & 15, ty = t >> 4;

    unsigned long long accp[4][2];
    #pragma unroll
    for (int i = 0; i < 4; i++) { accp[i][0] = 0ull; accp[i][1] = 0ull; }

    // -------- phase 1: S = q k^T over N --------
    for (int n0 = 0; n0 < N_; n0 += 64) {
        #pragma unroll
        for (int l = 0; l < 4; l++) {
            int i = t + l * 256;
            int nn = i >> 4, e4 = (i & 15) << 2;
            size_t ga = base + (size_t)(n0 + nn) * QS_ + e4;
            *(float4*)&b0[nn * 68 + e4] = *(const float4*)(qkv + ga);          // q
            *(float4*)&b1[nn * 68 + e4] = *(const float4*)(qkv + ga + 1024);  // k
        }
        __syncthreads();
        #pragma unroll 8
        for (int nn = 0; nn < 64; nn++) {
            float qa[4], kb[4];
            *(float4*)qa = *(const float4*)&b0[nn * 68 + ty * 4];
            *(float4*)kb = *(const float4*)&b1[nn * 68 + tx * 4];
            unsigned long long bp0 = pack2(kb[0], kb[1]);
            unsigned long long bp1 = pack2(kb[2], kb[3]);
            #pragma unroll
            for (int i = 0; i < 4; i++) {
                unsigned long long ap = pack2(qa[i], qa[i]);
                fma2(accp[i][0], ap, bp0);
                fma2(accp[i][1], ap, bp1);
            }
        }
        __syncthreads();
    }
    #pragma unroll
    for (int i = 0; i < 4; i++) {
        float2 p0 = unpack2(accp[i][0]), p1 = unpack2(accp[i][1]);
        float* Sr = &S[(ty * 4 + i) * 64 + tx * 4];
        Sr[0] = p0.x * 0.125f; Sr[1] = p0.y * 0.125f;
        Sr[2] = p1.x * 0.125f; Sr[3] = p1.y * 0.125f;
    }
    __syncthreads();

    // -------- phase 2: softmax rows --------
    if (t < 64) {
        float* Sr = S + t * 64;
        float mx = Sr[0];
        for (int f = 1; f < 64; f++) mx = fmaxf(mx, Sr[f]);
        float sum = 0.f;
        for (int f = 0; f < 64; f++) { float e = expf(Sr[f] - mx); Sr[f] = e; sum += e; }
        float inv = 1.f / sum;
        for (int f = 0; f < 64; f++) Sr[f] *= inv;
    }
    __syncthreads();

    // -------- phase 3: o = S @ v --------
    for (int n0 = 0; n0 < N_; n0 += 64) {
        #pragma unroll
        for (int l = 0; l < 4; l++) {
            int i = t + l * 256;
            int nn = i >> 4, f4 = (i & 15) << 2;
            float4 rv = *(const float4*)(qkv + base + (size_t)(n0 + nn) * QS_ + 2048 + f4);
            b0[(f4 + 0) * 68 + nn] = rv.x;
            b0[(f4 + 1) * 68 + nn] = rv.y;
            b0[(f4 + 2) * 68 + nn] = rv.z;
            b0[(f4 + 3) * 68 + nn] = rv.w;
        }
        __syncthreads();
        unsigned long long op[4][2];
        #pragma unroll
        for (int i = 0; i < 4; i++) { op[i][0] = 0ull; op[i][1] = 0ull; }
        #pragma unroll 8
        for (int f = 0; f < 64; f++) {
            float vb[4];
            *(float4*)vb = *(const float4*)&b0[f * 68 + tx * 4];
            unsigned long long bp0 = pack2(vb[0], vb[1]);
            unsigned long long bp1 = pack2(vb[2], vb[3]);
            #pragma unroll
            for (int i = 0; i < 4; i++) {
                float sv = S[(ty * 4 + i) * 64 + f];
                unsigned long long ap = pack2(sv, sv);
                fma2(op[i][0], ap, bp0);
                fma2(op[i][1], ap, bp1);
            }
        }
        #pragma unroll
        for (int i = 0; i < 4; i++) {
            float2 p0 = unpack2(op[i][0]), p1 = unpack2(op[i][1]);
            float* dr = &b1[(ty * 4 + i) * 68 + tx * 4];
            dr[0] = p0.x; dr[1] = p0.y; dr[2] = p1.x; dr[3] = p1.y;
        }
        __syncthreads();
        const size_t obase = (size_t)b * ((size_t)N_ * C_) +
                             (size_t)(h * 4 + (n0 >> 10)) * C_ + (n0 & 1023);
        #pragma unroll
        for (int l = 0; l < 4; l++) {
            int i = t + l * 256;
            int e = i >> 4, n4 = (i & 15) << 2;
            float4 vv = *(const float4*)&b1[e * 68 + n4];
            __half2 h01 = __floats2half2_rn(vv.x, vv.y);
            __half2 h23 = __floats2half2_rn(vv.z, vv.w);
            uint2 pk; pk.x = *(uint32_t*)&h01; pk.y = *(uint32_t*)&h23;
            *(uint2*)(o + obase + (size_t)e * 64 * C_ + n4) = pk;
        }
        __syncthreads();
    }
}

// ---------------- launch ----------------
extern "C" void kernel_launch(void* const* d_in, const int* in_sizes, int n_in,
                              void* d_out, int out_size) {
    const float* x      = (const float*)d_in[0];
    const float* ln1_g  = (const float*)d_in[1];
    const float* ln1_b  = (const float*)d_in[2];
    const float* ln2_g  = (const float*)d_in[3];
    const float* ln2_b  = (const float*)d_in[4];
    const float* wq     = (const float*)d_in[5];
    const float* wk     = (const float*)d_in[6];
    const float* wv     = (const float*)d_in[7];
    const float* proj_w = (const float*)d_in[8];
    const float* proj_b = (const float*)d_in[9];
    const float* fc1_w  = (const float*)d_in[10];
    const float* fc1_b  = (const float*)d_in[11];
    const float* fc2_w  = (const float*)d_in[12];
    const float* fc2_b  = (const float*)d_in[13];
    float* out = (float*)d_out;

    __half *ph, *po, *ph2, *pff, *pwqkv, *pwp, *pw1, *pw2;
    float *pqkv, *px1;
    cudaGetSymbolAddress((void**)&ph,    g_h);
    cudaGetSymbolAddress((void**)&pqkv,  g_qkv);
    cudaGetSymbolAddress((void**)&po,    g_o);
    cudaGetSymbolAddress((void**)&px1,   g_x1);
    cudaGetSymbolAddress((void**)&ph2,   g_h2);
    cudaGetSymbolAddress((void**)&pff,   g_ff);
    cudaGetSymbolAddress((void**)&pwqkv, g_wqkv);
    cudaGetSymbolAddress((void**)&pwp,   g_wp);
    cudaGetSymbolAddress((void**)&pw1,   g_w1);
    cudaGetSymbolAddress((void**)&pw2,   g_w2);

    const int GEMM_SMEM = 3 * 32768;          // 98304: 2 CTAs/SM possible
    cudaFuncSetAttribute(hgemm<0>, cudaFuncAttributeMaxDynamicSharedMemorySize, GEMM_SMEM);
    cudaFuncSetAttribute(hgemm<1>, cudaFuncAttributeMaxDynamicSharedMemorySize, GEMM_SMEM);
    cudaFuncSetAttribute(hgemm<2>, cudaFuncAttributeMaxDynamicSharedMemorySize, GEMM_SMEM);
    const int ATTN_SMEM = (64 * 64 + 2 * 64 * 68) * 4;
    cudaFuncSetAttribute(attn_kernel, cudaFuncAttributeMaxDynamicSharedMemorySize, ATTN_SMEM);

    dim3 tb32(32, 8);
    // launches 1-2: batched weight transpose
    wtrans4<<<dim3(C_ / 32, C_ / 32, 4), tb32>>>(wq, wk, wv, proj_w, pwqkv, pwp);
    wtrans2<<<dim3(HF_ / 32, HF_ / 32, 2), tb32>>>(fc1_w, fc2_w, pw1, pw2);
    // launch 3: h = LN1(x) -> fp16
    ln_half<<<M_, 256>>>(x, ln1_g, ln1_b, ph);
    // launch 4: fused qkv = h @ [wq|wk|wv]  (fp32 out, [M,3072])
    hgemm<0><<<dim3(QS_ / 128, M_ / 128), 256, GEMM_SMEM>>>(
        ph, pwqkv, nullptr, nullptr, pqkv, nullptr, C_, QS_);
    // launch 5: attention -> scrambled fp16 o
    attn_kernel<<<B_ * H_, 256, ATTN_SMEM>>>(pqkv, po);
    // launch 6 (ncu -s 5 captures this): x1 = x + o @ proj_w + proj_b
    hgemm<1><<<dim3(C_ / 128, M_ / 128), 256, GEMM_SMEM>>>(
        po, pwp, proj_b, x, px1, nullptr, C_, C_);
    // h2 = LN2(x1) -> fp16
    ln_half<<<M_, 256>>>(px1, ln2_g, ln2_b, ph2);
    // ff = gelu(h2 @ fc1_w + fc1_b) -> fp16
    hgemm<2><<<dim3(HF_ / 128, M_ / 128), 256, GEMM_SMEM>>>(
        ph2, pw1, fc1_b, nullptr, nullptr, pff, C_, HF_);
    // out = x1 + ff @ fc2_w + fc2_b
    hgemm<1><<<dim3(C_ / 128, M_ / 128), 256, GEMM_SMEM>>>(
        pff, pw2, fc2_b, px1, out, nullptr, HF_, C_);
}

// round 15
// speedup vs baseline: 1.2911x; 1.2911x over previous
#include <cuda_runtime.h>
#include <cuda_fp16.h>
#include <math.h>
#include <stdint.h>

#define B_  8
#define N_  4096
#define C_  1024
#define H_  16
#define HF_ 2048
#define M_  (B_*N_)   // 32768
#define QS_ 3072      // fused qkv row stride

// ---------------- scratch (device globals) ----------------
__device__ __half g_h  [(size_t)M_*C_];                       // ln1 out (fp16)
__device__ float  g_qkv[(size_t)M_*QS_];                      // q|k|v fused (fp32)
__device__ __half g_o  [(size_t)M_*C_];                       // scrambled attn out (fp16)
__device__ float  g_x1 [(size_t)M_*C_];
__device__ __half g_h2 [(size_t)M_*C_];
__device__ __half g_ff [(size_t)M_*HF_];
// transposed fp16 weights, [N,K] row-major (K contiguous)
__device__ __half g_wqkv[(size_t)QS_*C_];   // [3072, 1024] rows: q then k then v
__device__ __half g_wp[C_*C_];
__device__ __half g_w1[(size_t)C_*HF_];     // [HF, C]
__device__ __half g_w2[(size_t)C_*HF_];     // [C, HF]

// ---------------- PTX helpers ----------------
#define SWZ(x) ((x) ^ (((x) >> 3) & 0x70))

__device__ __forceinline__ uint32_t s2u(const void* p) {
    uint32_t a;
    asm("{ .reg .u64 t; cvta.to.shared.u64 t, %1; cvt.u32.u64 %0, t; }" : "=r"(a) : "l"(p));
    return a;
}
__device__ __forceinline__ void cpa16(uint32_t d, const void* s) {
    asm volatile("cp.async.cg.shared.global [%0], [%1], 16;" :: "r"(d), "l"(s));
}
__device__ __forceinline__ void cp_commit() { asm volatile("cp.async.commit_group;"); }
__device__ __forceinline__ void cp_wait1()  { asm volatile("cp.async.wait_group 1;"); }
__device__ __forceinline__ void cp_wait0()  { asm volatile("cp.async.wait_group 0;"); }

__device__ __forceinline__ void ldsm_x4(uint32_t* r, uint32_t a) {
    asm volatile("ldmatrix.sync.aligned.m8n8.x4.shared.b16 {%0,%1,%2,%3}, [%4];"
                 : "=r"(r[0]), "=r"(r[1]), "=r"(r[2]), "=r"(r[3]) : "r"(a));
}
__device__ __forceinline__ void mma16816(float* c, const uint32_t* a, const uint32_t* b) {
    asm volatile("mma.sync.aligned.m16n8k16.row.col.f32.f16.f16.f32 "
                 "{%0,%1,%2,%3}, {%4,%5,%6,%7}, {%8,%9}, {%0,%1,%2,%3};"
                 : "+f"(c[0]), "+f"(c[1]), "+f"(c[2]), "+f"(c[3])
                 : "r"(a[0]), "r"(a[1]), "r"(a[2]), "r"(a[3]), "r"(b[0]), "r"(b[1]));
}
// packed f32x2 FMA (sm_103)
__device__ __forceinline__ unsigned long long pack2(float lo, float hi) {
    unsigned long long r;
    asm("mov.b64 %0, {%1, %2};" : "=l"(r) : "f"(lo), "f"(hi));
    return r;
}
__device__ __forceinline__ void fma2(unsigned long long& c, unsigned long long a,
                                     unsigned long long b) {
    asm("fma.rn.f32x2 %0, %1, %2, %0;" : "+l"(c) : "l"(a), "l"(b));
}
__device__ __forceinline__ float2 unpack2(unsigned long long p) {
    float2 r;
    asm("mov.b64 {%0, %1}, %2;" : "=f"(r.x), "=f"(r.y) : "l"(p));
    return r;
}

// ---------------- batched weight transpose (fp32 [K,N] -> fp16 [N,K]) -------------
__device__ __forceinline__ void wtrans_tile(const float* __restrict__ W, int K, int N,
                                            __half* __restrict__ Wt) {
    __shared__ float tile[32][33];
    const int n0 = blockIdx.x * 32, k0 = blockIdx.y * 32;
    const int tx = threadIdx.x, ty = threadIdx.y;
    for (int i = ty; i < 32; i += 8)
        tile[i][tx] = W[(size_t)(k0 + i) * N + n0 + tx];
    __syncthreads();
    for (int i = ty; i < 32; i += 8)
        Wt[(size_t)(n0 + i) * K + k0 + tx] = __float2half_rn(tile[tx][i]);
}
__global__ void wtrans4(const float* __restrict__ wq, const float* __restrict__ wk,
                        const float* __restrict__ wv, const float* __restrict__ wp,
                        __half* __restrict__ wqkv, __half* __restrict__ wpd) {
    const int z = blockIdx.z;
    const float* W = (z == 0) ? wq : (z == 1) ? wk : (z == 2) ? wv : wp;
    __half* dst = (z < 3) ? (wqkv + (size_t)z * C_ * C_) : wpd;
    wtrans_tile(W, C_, C_, dst);
}
__global__ void wtrans2(const float* __restrict__ fc1, const float* __restrict__ fc2,
                        __half* __restrict__ w1, __half* __restrict__ w2) {
    const int z = blockIdx.z;
    if (z == 0) {  // fc1 [C, HF] -> [HF, C]
        if (blockIdx.y >= C_ / 32) return;
        wtrans_tile(fc1, C_, HF_, w1);
    } else {       // fc2 [HF, C] -> [C, HF]
        if (blockIdx.x >= C_ / 32) return;
        wtrans_tile(fc2, HF_, C_, w2);
    }
}

// ---------------- LayerNorm (fp32 in, fp16 out) ----------------
__global__ void __launch_bounds__(256) ln_half(const float* __restrict__ x,
                                               const float* __restrict__ g,
                                               const float* __restrict__ b,
                                               __half* __restrict__ out) {
    const size_t row = blockIdx.x;
    const int t = threadIdx.x;
    float4 v = ((const float4*)(x + row * C_))[t];

    float s  = v.x + v.y + v.z + v.w;
    float sq = v.x * v.x + v.y * v.y + v.z * v.z + v.w * v.w;
    #pragma unroll
    for (int o = 16; o; o >>= 1) {
        s  += __shfl_xor_sync(0xffffffffu, s, o);
        sq += __shfl_xor_sync(0xffffffffu, sq, o);
    }
    __shared__ float ss[8], ssq[8];
    if ((t & 31) == 0) { ss[t >> 5] = s; ssq[t >> 5] = sq; }
    __syncthreads();
    s = 0.f; sq = 0.f;
    #pragma unroll
    for (int i = 0; i < 8; i++) { s += ss[i]; sq += ssq[i]; }

    const float mu  = s * (1.0f / C_);
    const float var = sq * (1.0f / C_) - mu * mu;
    const float rs  = rsqrtf(var + 1e-5f);

    float4 gg = ((const float4*)g)[t];
    float4 bb = ((const float4*)b)[t];
    __half2 h01 = __floats2half2_rn((v.x - mu) * rs * gg.x + bb.x,
                                    (v.y - mu) * rs * gg.y + bb.y);
    __half2 h23 = __floats2half2_rn((v.z - mu) * rs * gg.z + bb.z,
                                    (v.w - mu) * rs * gg.w + bb.w);
    uint2 pk; pk.x = *(uint32_t*)&h01; pk.y = *(uint32_t*)&h23;
    *(uint2*)(out + row * C_ + t * 4) = pk;
}

// ---------------- HMMA GEMM: 128x128 tile, BK=64, 3-stage cp.async, -----------------
// fragment double-buffering across ks steps; 2 CTAs/SM locked via launch bounds.
// EPI: 0 = fp32 out; 1 = +bias +resid, fp32 out; 2 = +bias, exact GELU, fp16 out.
template <int EPI>
__global__ void __launch_bounds__(256, 2) hgemm(const __half* __restrict__ A,
                                                const __half* __restrict__ Bt,
                                                const float* __restrict__ bias,
                                                const float* __restrict__ resid,
                                                float* __restrict__ outF,
                                                __half* __restrict__ outH,
                                                int K, int N) {
    extern __shared__ char smem[];
    const uint32_t sb = s2u(smem);

    const int t = threadIdx.x;
    const int lane = t & 31, wid = t >> 5;
    const int wm = wid & 1, wn = wid >> 1;     // warp grid 2(m) x 4(n)
    const int bm = blockIdx.y << 7;
    const int bn = blockIdx.x << 7;
    const int NK = K >> 6;

    float acc[4][4][4];
    #pragma unroll
    for (int i = 0; i < 4; i++)
        #pragma unroll
        for (int j = 0; j < 4; j++)
            #pragma unroll
            for (int e = 0; e < 4; e++) acc[i][j][e] = 0.f;

    // per-thread gmem load geometry
    const uint32_t swz0 = SWZ((uint32_t)((t >> 3) * 128 + (t & 7) * 16));
    const __half* gA = A  + (size_t)(bm + (t >> 3)) * K + (t & 7) * 8;
    const __half* gB = Bt + (size_t)(bn + (t >> 3)) * K + (t & 7) * 8;
    const size_t lstride = (size_t)32 * K;

    auto fill = [&](int stage, int k0) {
        const uint32_t base = sb + stage * 32768;
        #pragma unroll
        for (int l = 0; l < 4; l++)
            cpa16(base + swz0 + l * 4096, gA + l * lstride + k0);
        #pragma unroll
        for (int l = 0; l < 4; l++)
            cpa16(base + 16384 + swz0 + l * 4096, gB + l * lstride + k0);
        cp_commit();
    };

    fill(0, 0);
    fill(1, 64);

    // ldsm address precompute (per-thread, ks-dependent part added later).
    const uint32_t aRow = (uint32_t)(wm * 64 + (lane & 15));
    const uint32_t aColHalf = (uint32_t)((lane >> 4) * 16);
    const uint32_t bRow = (uint32_t)(wn * 32 + ((lane >> 4) & 1) * 8 + (lane & 7));
    const uint32_t bColHalf = (uint32_t)(((lane >> 3) & 1) * 16);

    uint32_t afr[2][4][4], bfr[2][4][2];

    auto ldfrag = [&](int fb, int ks, uint32_t aB, uint32_t bB) {
        const uint32_t kc = (uint32_t)(ks * 32);
        #pragma unroll
        for (int i = 0; i < 4; i++) {
            uint32_t off = (aRow + i * 16) * 128 + kc + aColHalf;
            ldsm_x4(afr[fb][i], aB + SWZ(off));
        }
        #pragma unroll
        for (int jp = 0; jp < 2; jp++) {
            uint32_t off = (bRow + jp * 16) * 128 + kc + bColHalf;
            uint32_t r[4];
            ldsm_x4(r, bB + SWZ(off));
            bfr[fb][jp * 2][0]     = r[0]; bfr[fb][jp * 2][1]     = r[1];
            bfr[fb][jp * 2 + 1][0] = r[2]; bfr[fb][jp * 2 + 1][1] = r[3];
        }
    };

    for (int ch = 0; ch < NK; ch++) {
        const int buf = ch % 3;
        if (ch == NK - 1) cp_wait0(); else cp_wait1();
        __syncthreads();
        // prefetch gmem into the slot consumed LAST iteration
        if (ch + 2 < NK) fill((ch + 2) % 3, (ch + 2) << 6);

        const uint32_t aB = sb + buf * 32768;
        const uint32_t bB = aB + 16384;
        ldfrag(0, 0, aB, bB);
        #pragma unroll
        for (int ks = 0; ks < 4; ks++) {
            const int cur = ks & 1;
            if (ks < 3) ldfrag(cur ^ 1, ks + 1, aB, bB);
            #pragma unroll
            for (int i = 0; i < 4; i++)
                #pragma unroll
                for (int j = 0; j < 4; j++)
                    mma16816(acc[i][j], afr[cur][i], bfr[cur][j]);
        }
    }
    __syncthreads();

    // -------- epilogue: frags -> smem fp32 [128][132] -> coalesced gmem --------
    float* st = (float*)smem;
    #pragma unroll
    for (int i = 0; i < 4; i++) {
        const int r0 = wm * 64 + i * 16 + (lane >> 2);
        #pragma unroll
        for (int j = 0; j < 4; j++) {
            const int c0 = wn * 32 + j * 8 + 2 * (lane & 3);
            st[r0 * 132 + c0]             = acc[i][j][0];
            st[r0 * 132 + c0 + 1]         = acc[i][j][1];
            st[(r0 + 8) * 132 + c0]       = acc[i][j][2];
            st[(r0 + 8) * 132 + c0 + 1]   = acc[i][j][3];
        }
    }
    __syncthreads();
    #pragma unroll
    for (int l = 0; l < 16; l++) {
        int idx = t + 256 * l;
        int row = idx >> 5, c4 = (idx & 31) << 2;
        const float* src = st + row * 132 + c4;
        float v0 = src[0], v1 = src[1], v2 = src[2], v3 = src[3];
        const int col = bn + c4;
        const size_t go = (size_t)(bm + row) * N + col;
        if (EPI == 0) {
            *(float4*)(outF + go) = make_float4(v0, v1, v2, v3);
        } else if (EPI == 1) {
            const float4 bb = *(const float4*)(bias + col);
            const float4 rr = *(const float4*)(resid + go);
            *(float4*)(outF + go) = make_float4(v0 + bb.x + rr.x, v1 + bb.y + rr.y,
                                                v2 + bb.z + rr.z, v3 + bb.w + rr.w);
        } else {
            const float4 bb = *(const float4*)(bias + col);
            float x0 = v0 + bb.x, x1 = v1 + bb.y, x2 = v2 + bb.z, x3 = v3 + bb.w;
            const float ki = 0.70710678118654752f;
            x0 = 0.5f * x0 * (1.0f + erff(x0 * ki));
            x1 = 0.5f * x1 * (1.0f + erff(x1 * ki));
            x2 = 0.5f * x2 * (1.0f + erff(x2 * ki));
            x3 = 0.5f * x3 * (1.0f + erff(x3 * ki));
            __half2 h01 = __floats2half2_rn(x0, x1);
            __half2 h23 = __floats2half2_rn(x2, x3);
            uint2 pk; pk.x = *(uint32_t*)&h01; pk.y = *(uint32_t*)&h23;
            *(uint2*)(outH + go) = pk;
        }
    }
}

// ---------------- fused attention (fp32 qkv in [M,3072], fp16 scrambled out) --------
// o_merged[b, e*64 + h*4 + (n>>10), n&1023] = o[b,h,e,n]
__global__ void __launch_bounds__(256) attn_kernel(const float* __restrict__ qkv,
                                                   __half* __restrict__ o) {
    extern __shared__ float sm[];
    float* S  = sm;                         // 64*64
    float* b0 = sm + 64 * 64;               // 64*68
    float* b1 = sm + 64 * 64 + 64 * 68;     // 64*68

    const int bh = blockIdx.x;
    const int b = bh >> 4, h = bh & 15;
    const size_t base = (size_t)b * ((size_t)N_ * QS_) + (size_t)h * 64;
    const int t  = threadIdx.x;
    const int tx = t & 15, ty = t >> 4;

    unsigned long long accp[4][2];
    #pragma unroll
    for (int i = 0; i < 4; i++) { accp[i][0] = 0ull; accp[i][1] = 0ull; }

    // -------- phase 1: S = q k^T over N --------
    for (int n0 = 0; n0 < N_; n0 += 64) {
        #pragma unroll
        for (int l = 0; l < 4; l++) {
            int i = t + l * 256;
            int nn = i >> 4, e4 = (i & 15) << 2;
            size_t ga = base + (size_t)(n0 + nn) * QS_ + e4;
            *(float4*)&b0[nn * 68 + e4] = *(const float4*)(qkv + ga);          // q
            *(float4*)&b1[nn * 68 + e4] = *(const float4*)(qkv + ga + 1024);  // k
        }
        __syncthreads();
        #pragma unroll 8
        for (int nn = 0; nn < 64; nn++) {
            float qa[4], kb[4];
            *(float4*)qa = *(const float4*)&b0[nn * 68 + ty * 4];
            *(float4*)kb = *(const float4*)&b1[nn * 68 + tx * 4];
            unsigned long long bp0 = pack2(kb[0], kb[1]);
            unsigned long long bp1 = pack2(kb[2], kb[3]);
            #pragma unroll
            for (int i = 0; i < 4; i++) {
                unsigned long long ap = pack2(qa[i], qa[i]);
                fma2(accp[i][0], ap, bp0);
                fma2(accp[i][1], ap, bp1);
            }
        }
        __syncthreads();
    }
    #pragma unroll
    for (int i = 0; i < 4; i++) {
        float2 p0 = unpack2(accp[i][0]), p1 = unpack2(accp[i][1]);
        float* Sr = &S[(ty * 4 + i) * 64 + tx * 4];
        Sr[0] = p0.x * 0.125f; Sr[1] = p0.y * 0.125f;
        Sr[2] = p1.x * 0.125f; Sr[3] = p1.y * 0.125f;
    }
    __syncthreads();

    // -------- phase 2: softmax rows --------
    if (t < 64) {
        float* Sr = S + t * 64;
        float mx = Sr[0];
        for (int f = 1; f < 64; f++) mx = fmaxf(mx, Sr[f]);
        float sum = 0.f;
        for (int f = 0; f < 64; f++) { float e = expf(Sr[f] - mx); Sr[f] = e; sum += e; }
        float inv = 1.f / sum;
        for (int f = 0; f < 64; f++) Sr[f] *= inv;
    }
    __syncthreads();

    // -------- phase 3: o = S @ v --------
    for (int n0 = 0; n0 < N_; n0 += 64) {
        #pragma unroll
        for (int l = 0; l < 4; l++) {
            int i = t + l * 256;
            int nn = i >> 4, f4 = (i & 15) << 2;
            float4 rv = *(const float4*)(qkv + base + (size_t)(n0 + nn) * QS_ + 2048 + f4);
            b0[(f4 + 0) * 68 + nn] = rv.x;
            b0[(f4 + 1) * 68 + nn] = rv.y;
            b0[(f4 + 2) * 68 + nn] = rv.z;
            b0[(f4 + 3) * 68 + nn] = rv.w;
        }
        __syncthreads();
        unsigned long long op[4][2];
        #pragma unroll
        for (int i = 0; i < 4; i++) { op[i][0] = 0ull; op[i][1] = 0ull; }
        #pragma unroll 8
        for (int f = 0; f < 64; f++) {
            float vb[4];
            *(float4*)vb = *(const float4*)&b0[f * 68 + tx * 4];
            unsigned long long bp0 = pack2(vb[0], vb[1]);
            unsigned long long bp1 = pack2(vb[2], vb[3]);
            #pragma unroll
            for (int i = 0; i < 4; i++) {
                float sv = S[(ty * 4 + i) * 64 + f];
                unsigned long long ap = pack2(sv, sv);
                fma2(op[i][0], ap, bp0);
                fma2(op[i][1], ap, bp1);
            }
        }
        #pragma unroll
        for (int i = 0; i < 4; i++) {
            float2 p0 = unpack2(op[i][0]), p1 = unpack2(op[i][1]);
            float* dr = &b1[(ty * 4 + i) * 68 + tx * 4];
            dr[0] = p0.x; dr[1] = p0.y; dr[2] = p1.x; dr[3] = p1.y;
        }
        __syncthreads();
        const size_t obase = (size_t)b * ((size_t)N_ * C_) +
                             (size_t)(h * 4 + (n0 >> 10)) * C_ + (n0 & 1023);
        #pragma unroll
        for (int l = 0; l < 4; l++) {
            int i = t + l * 256;
            int e = i >> 4, n4 = (i & 15) << 2;
            float4 vv = *(const float4*)&b1[e * 68 + n4];
            __half2 h01 = __floats2half2_rn(vv.x, vv.y);
            __half2 h23 = __floats2half2_rn(vv.z, vv.w);
            uint2 pk; pk.x = *(uint32_t*)&h01; pk.y = *(uint32_t*)&h23;
            *(uint2*)(o + obase + (size_t)e * 64 * C_ + n4) = pk;
        }
        __syncthreads();
    }
}

// ---------------- launch ----------------
extern "C" void kernel_launch(void* const* d_in, const int* in_sizes, int n_in,
                              void* d_out, int out_size) {
    const float* x      = (const float*)d_in[0];
    const float* ln1_g  = (const float*)d_in[1];
    const float* ln1_b  = (const float*)d_in[2];
    const float* ln2_g  = (const float*)d_in[3];
    const float* ln2_b  = (const float*)d_in[4];
    const float* wq     = (const float*)d_in[5];
    const float* wk     = (const float*)d_in[6];
    const float* wv     = (const float*)d_in[7];
    const float* proj_w = (const float*)d_in[8];
    const float* proj_b = (const float*)d_in[9];
    const float* fc1_w  = (const float*)d_in[10];
    const float* fc1_b  = (const float*)d_in[11];
    const float* fc2_w  = (const float*)d_in[12];
    const float* fc2_b  = (const float*)d_in[13];
    float* out = (float*)d_out;

    __half *ph, *po, *ph2, *pff, *pwqkv, *pwp, *pw1, *pw2;
    float *pqkv, *px1;
    cudaGetSymbolAddress((void**)&ph,    g_h);
    cudaGetSymbolAddress((void**)&pqkv,  g_qkv);
    cudaGetSymbolAddress((void**)&po,    g_o);
    cudaGetSymbolAddress((void**)&px1,   g_x1);
    cudaGetSymbolAddress((void**)&ph2,   g_h2);
    cudaGetSymbolAddress((void**)&pff,   g_ff);
    cudaGetSymbolAddress((void**)&pwqkv, g_wqkv);
    cudaGetSymbolAddress((void**)&pwp,   g_wp);
    cudaGetSymbolAddress((void**)&pw1,   g_w1);
    cudaGetSymbolAddress((void**)&pw2,   g_w2);

    const int GEMM_SMEM = 3 * 32768;          // 98304: 2 CTAs/SM
    cudaFuncSetAttribute(hgemm<0>, cudaFuncAttributeMaxDynamicSharedMemorySize, GEMM_SMEM);
    cudaFuncSetAttribute(hgemm<1>, cudaFuncAttributeMaxDynamicSharedMemorySize, GEMM_SMEM);
    cudaFuncSetAttribute(hgemm<2>, cudaFuncAttributeMaxDynamicSharedMemorySize, GEMM_SMEM);
    const int ATTN_SMEM = (64 * 64 + 2 * 64 * 68) * 4;
    cudaFuncSetAttribute(attn_kernel, cudaFuncAttributeMaxDynamicSharedMemorySize, ATTN_SMEM);

    dim3 tb32(32, 8);
    // launches 1-2: batched weight transpose
    wtrans4<<<dim3(C_ / 32, C_ / 32, 4), tb32>>>(wq, wk, wv, proj_w, pwqkv, pwp);
    wtrans2<<<dim3(HF_ / 32, HF_ / 32, 2), tb32>>>(fc1_w, fc2_w, pw1, pw2);
    // launch 3: h = LN1(x) -> fp16
    ln_half<<<M_, 256>>>(x, ln1_g, ln1_b, ph);
    // launch 4: fused qkv = h @ [wq|wk|wv]  (fp32 out, [M,3072])
    hgemm<0><<<dim3(QS_ / 128, M_ / 128), 256, GEMM_SMEM>>>(
        ph, pwqkv, nullptr, nullptr, pqkv, nullptr, C_, QS_);
    // launch 5: attention -> scrambled fp16 o
    attn_kernel<<<B_ * H_, 256, ATTN_SMEM>>>(pqkv, po);
    // launch 6 (ncu -s 5 captures this): x1 = x + o @ proj_w + proj_b
    hgemm<1><<<dim3(C_ / 128, M_ / 128), 256, GEMM_SMEM>>>(
        po, pwp, proj_b, x, px1, nullptr, C_, C_);
    // h2 = LN2(x1) -> fp16
    ln_half<<<M_, 256>>>(px1, ln2_g, ln2_b, ph2);
    // ff = gelu(h2 @ fc1_w + fc1_b) -> fp16
    hgemm<2><<<dim3(HF_ / 128, M_ / 128), 256, GEMM_SMEM>>>(
        ph2, pw1, fc1_b, nullptr, nullptr, pff, C_, HF_);
    // out = x1 + ff @ fc2_w + fc2_b
    hgemm<1><<<dim3(C_ / 128, M_ / 128), 256, GEMM_SMEM>>>(
        pff, pw2, fc2_b, px1, out, nullptr, HF_, C_);
}